// round 1
// baseline (speedup 1.0000x reference)
#include <cuda_runtime.h>

// ---------------------------------------------------------------------------
// unit_aagcn: N=64, C=OC=64, T=300, V=25, S=3, IC=16
//
// K1: fused conv_a/conv_b + BN + tanh + M accumulation  -> g_Mpart
// K3: A_adp = A + tanh(sum(Mpart)/4800)*alpha (in smem),
//     z[s,o,v] = Wd_s @ x_t,  y[o,w] = sum_{s,v} z * A_adp,
//     out = relu(bn(y + sum_s bd) + x)
// ---------------------------------------------------------------------------

#define N_  64
#define C_  64
#define T_  300
#define V_  25
#define S_  3
#define IC_ 16

#define TCH1 5           // K1 t-chunks  (60 t per block, processed 2 at a time)
#define T1   (T_ / TCH1) // 60
#define TCH3 15          // K3 t-chunks  (20 t per block)
#define T3   (T_ / TCH3) // 20

// M partials: [n][s][tc][v][w]  (64*3*5*625 floats = 2.4 MB scratch)
__device__ float g_Mpart[N_ * S_ * TCH1 * V_ * V_];

__device__ __forceinline__ float fast_tanh(float x) {
    // tanh(x) = 1 - 2/(exp(2x)+1); __expf saturates cleanly at +/-inf
    float e = __expf(2.0f * x);
    return 1.0f - __fdividef(2.0f, e + 1.0f);
}

// ---------------------------------------------------------------------------
// K1: one block per (t-chunk, s, n). 160 threads.
//   conv phase: threads map to (t_off in 2, i in 16, vgroup in 5) -> 10 FMA / 7 LDS
//   M phase:    threads 0..124 map to (v, wgroup of 5); m[5] persists over t-loop
// ---------------------------------------------------------------------------
__global__ void __launch_bounds__(160)
k1_conv_M(const float* __restrict__ x,
          const float* __restrict__ wa, const float* __restrict__ ba,
          const float* __restrict__ wb, const float* __restrict__ bb,
          const float* __restrict__ ga, const float* __restrict__ bea,
          const float* __restrict__ ma, const float* __restrict__ va,
          const float* __restrict__ gb, const float* __restrict__ beb,
          const float* __restrict__ mb, const float* __restrict__ vb)
{
    const int tc = blockIdx.x;
    const int s  = blockIdx.y;
    const int n  = blockIdx.z;
    const int tid = threadIdx.x;

    __shared__ float WaT[C_ * IC_];   // [c][i] transposed (conflict-free)
    __shared__ float WbT[C_ * IC_];
    __shared__ float sA[IC_], cA[IC_], sB[IC_], cB[IC_];
    __shared__ float xs[C_ * 50];     // two t's: [c][2*25]
    __shared__ float a_sm[2 * IC_ * V_];
    __shared__ float b_sm[2 * IC_ * V_];

    for (int idx = tid; idx < IC_ * C_; idx += 160) {
        int i = idx / C_, c = idx % C_;
        WaT[c * IC_ + i] = wa[(s * IC_ + i) * C_ + c];
        WbT[c * IC_ + i] = wb[(s * IC_ + i) * C_ + c];
    }
    if (tid < IC_) {
        int i = tid;
        float sa = ga[s * IC_ + i] * rsqrtf(va[s * IC_ + i] + 1e-5f);
        sA[i] = sa;
        cA[i] = sa * (ba[s * IC_ + i] - ma[s * IC_ + i]) + bea[s * IC_ + i];
        float sb = gb[s * IC_ + i] * rsqrtf(vb[s * IC_ + i] + 1e-5f);
        sB[i] = sb;
        cB[i] = sb * (bb[s * IC_ + i] - mb[s * IC_ + i]) + beb[s * IC_ + i];
    }

    // conv-phase mapping (all 160 threads)
    const int toff = tid / 80;          // which of the two t's
    const int r    = tid % 80;
    const int ii   = r & 15;            // i channel
    const int vg   = r >> 4;            // v group (5 v's)

    // M-phase mapping (threads < 125)
    const int vv = tid / 5;
    const int wg = tid % 5;

    float m[5] = {0.f, 0.f, 0.f, 0.f, 0.f};
    const int t0 = tc * T1;
    __syncthreads();

    for (int tp = 0; tp < T1; tp += 2) {
        const int t = t0 + tp;
        // load x[n, :, t..t+1, :] -> xs[c][50] (contiguous 50 floats per c)
        for (int idx = tid; idx < C_ * 50; idx += 160) {
            int c = idx / 50, j = idx % 50;
            xs[idx] = x[((n * C_ + c) * T_ + t) * V_ + j];
        }
        __syncthreads();

        {
            float acca[5] = {0.f, 0.f, 0.f, 0.f, 0.f};
            float accb[5] = {0.f, 0.f, 0.f, 0.f, 0.f};
            const float* xrow = xs + toff * 25 + vg * 5;
            #pragma unroll 8
            for (int c = 0; c < C_; c++) {
                float wav = WaT[c * IC_ + ii];
                float wbv = WbT[c * IC_ + ii];
                #pragma unroll
                for (int k = 0; k < 5; k++) {
                    float xv = xrow[c * 50 + k];
                    acca[k] = fmaf(wav, xv, acca[k]);
                    accb[k] = fmaf(wbv, xv, accb[k]);
                }
            }
            float sa = sA[ii], ca = cA[ii], sb = sB[ii], cb = cB[ii];
            float* ap = a_sm + (toff * IC_ + ii) * V_ + vg * 5;
            float* bp = b_sm + (toff * IC_ + ii) * V_ + vg * 5;
            #pragma unroll
            for (int k = 0; k < 5; k++) {
                ap[k] = fast_tanh(fmaf(sa, acca[k], ca));
                bp[k] = fast_tanh(fmaf(sb, accb[k], cb));
            }
        }
        __syncthreads();

        if (tid < 125) {
            #pragma unroll
            for (int t2 = 0; t2 < 2; t2++) {
                const float* ap = a_sm + t2 * IC_ * V_;
                const float* bp = b_sm + t2 * IC_ * V_ + wg * 5;
                #pragma unroll 4
                for (int i = 0; i < IC_; i++) {
                    float av = ap[i * V_ + vv];
                    #pragma unroll
                    for (int k = 0; k < 5; k++)
                        m[k] = fmaf(av, bp[i * V_ + k], m[k]);
                }
            }
        }
        __syncthreads();
    }

    if (tid < 125) {
        float* dst = g_Mpart + ((((n * S_ + s) * TCH1 + tc) * V_ + vv) * V_) + wg * 5;
        #pragma unroll
        for (int k = 0; k < 5; k++) dst[k] = m[k];
    }
}

// ---------------------------------------------------------------------------
// K3: one block per (t-chunk, n). 256 threads, ~82 KB dynamic smem.
// ---------------------------------------------------------------------------
// smem layout (bytes, 16B aligned)
#define OFF_WDT   0                         // 3*64*64*4 = 49152  [s][c][o]
#define OFF_AA    49152                     // 3*625*4   = 7500 -> pad 7504
#define OFF_XS    (49152 + 7504)            // 64*25*4   = 6400
#define OFF_ZS    (OFF_XS + 6400)           // 3*25*64*4 = 19200  [s][v][o]
#define OFF_SC    (OFF_ZS + 19200)          // 64*4
#define OFF_SH    (OFF_SC + 256)            // 64*4
#define SMEM3     (OFF_SH + 256)

__global__ void __launch_bounds__(256)
k3_out(const float* __restrict__ x,
       const float* __restrict__ A, const float* __restrict__ alpha,
       const float* __restrict__ wd, const float* __restrict__ bd,
       const float* __restrict__ bng, const float* __restrict__ bnb,
       const float* __restrict__ bnm, const float* __restrict__ bnv,
       float* __restrict__ out)
{
    extern __shared__ char smem[];
    float* WdT   = (float*)(smem + OFF_WDT);   // [s][c][o]
    float* Aa    = (float*)(smem + OFF_AA);    // [s][v][w]
    float* xs    = (float*)(smem + OFF_XS);    // [c][v]
    float* zs    = (float*)(smem + OFF_ZS);    // [s][v][o]
    float* scl   = (float*)(smem + OFF_SC);
    float* shf   = (float*)(smem + OFF_SH);

    const int tc  = blockIdx.x;
    const int n   = blockIdx.y;
    const int tid = threadIdx.x;

    // Wd transposed into smem
    for (int idx = tid; idx < S_ * C_ * C_; idx += 256) {
        int s = idx >> 12, rem = idx & 4095, o = rem >> 6, c = rem & 63;
        WdT[(s << 12) + (c << 6) + o] = wd[idx];
    }
    // A_adp from M partials
    {
        float al = alpha[0];
        for (int idx = tid; idx < S_ * V_ * V_; idx += 256) {
            int s = idx / (V_ * V_), vwi = idx % (V_ * V_);
            const float* mp = g_Mpart + ((n * S_ + s) * TCH1) * (V_ * V_) + vwi;
            float msum = 0.f;
            #pragma unroll
            for (int p = 0; p < TCH1; p++) msum += mp[p * (V_ * V_)];
            Aa[idx] = A[idx] + tanhf(msum * (1.0f / (IC_ * T_))) * al;
        }
    }
    if (tid < C_) {
        float sc = bng[tid] * rsqrtf(bnv[tid] + 1e-5f);
        float db = bd[tid] + bd[C_ + tid] + bd[2 * C_ + tid];
        scl[tid] = sc;
        shf[tid] = bnb[tid] + sc * (db - bnm[tid]);
    }

    // phase Z mapping: tid<240 -> (s, o-group of 4, v-group of 5)
    const int sZ  = tid / 80;
    const int rZ  = tid % 80;
    const int ogZ = rZ & 15;
    const int vgZ = rZ >> 4;
    // phase Y mapping: tid<160 -> (o-group of 2, w-group of 5)
    const int ogY = tid & 31;
    const int wgY = tid >> 5;

    const int t0 = tc * T3;
    __syncthreads();

    for (int tp = 0; tp < T3; tp++) {
        const int t = t0 + tp;
        for (int idx = tid; idx < C_ * V_; idx += 256) {
            int c = idx / V_, v = idx % V_;
            xs[idx] = x[((n * C_ + c) * T_ + t) * V_ + v];
        }
        __syncthreads();

        // phase Z: z[s][v][o] = sum_c Wd[s][o][c] * x[c][v]
        if (tid < 240) {
            float acc[4][5];
            #pragma unroll
            for (int j = 0; j < 4; j++)
                #pragma unroll
                for (int k = 0; k < 5; k++) acc[j][k] = 0.f;

            const float* wbase = WdT + (sZ << 12) + ogZ * 4;
            const float* xbase = xs + vgZ * 5;
            #pragma unroll 4
            for (int c = 0; c < C_; c++) {
                float4 w4 = *(const float4*)(wbase + (c << 6));
                const float* xc = xbase + c * V_;
                #pragma unroll
                for (int k = 0; k < 5; k++) {
                    float xv = xc[k];
                    acc[0][k] = fmaf(w4.x, xv, acc[0][k]);
                    acc[1][k] = fmaf(w4.y, xv, acc[1][k]);
                    acc[2][k] = fmaf(w4.z, xv, acc[2][k]);
                    acc[3][k] = fmaf(w4.w, xv, acc[3][k]);
                }
            }
            #pragma unroll
            for (int k = 0; k < 5; k++) {
                float4 zv = make_float4(acc[0][k], acc[1][k], acc[2][k], acc[3][k]);
                *(float4*)(zs + ((sZ * V_ + vgZ * 5 + k) << 6) + ogZ * 4) = zv;
            }
        }
        __syncthreads();

        // phase Y: y[o][w] = sum_{s,v} z[s][v][o] * Aa[s][v][w]  + epilogue
        if (tid < 160) {
            float acc[2][5];
            #pragma unroll
            for (int j = 0; j < 2; j++)
                #pragma unroll
                for (int k = 0; k < 5; k++) acc[j][k] = 0.f;

            #pragma unroll 5
            for (int sv = 0; sv < S_ * V_; sv++) {
                float2 z2 = *(const float2*)(zs + (sv << 6) + ogY * 2);
                const float* ar = Aa + sv * V_ + wgY * 5;
                #pragma unroll
                for (int k = 0; k < 5; k++) {
                    float aw = ar[k];
                    acc[0][k] = fmaf(z2.x, aw, acc[0][k]);
                    acc[1][k] = fmaf(z2.y, aw, acc[1][k]);
                }
            }
            #pragma unroll
            for (int j = 0; j < 2; j++) {
                int o = ogY * 2 + j;
                float sc = scl[o], sh = shf[o];
                float* op = out + ((n * C_ + o) * T_ + t) * V_ + wgY * 5;
                const float* xr = xs + o * V_ + wgY * 5;
                #pragma unroll
                for (int k = 0; k < 5; k++) {
                    float yv = fmaf(sc, acc[j][k], sh) + xr[k];
                    op[k] = fmaxf(yv, 0.0f);
                }
            }
        }
        __syncthreads();
    }
}

// ---------------------------------------------------------------------------
extern "C" void kernel_launch(void* const* d_in, const int* in_sizes, int n_in,
                              void* d_out, int out_size)
{
    const float* x        = (const float*)d_in[0];
    const float* A        = (const float*)d_in[1];
    const float* alpha    = (const float*)d_in[2];
    const float* conv_a_w = (const float*)d_in[3];
    const float* conv_a_b = (const float*)d_in[4];
    const float* conv_b_w = (const float*)d_in[5];
    const float* conv_b_b = (const float*)d_in[6];
    const float* bn_a_g   = (const float*)d_in[7];
    const float* bn_a_be  = (const float*)d_in[8];
    const float* bn_a_m   = (const float*)d_in[9];
    const float* bn_a_v   = (const float*)d_in[10];
    const float* bn_b_g   = (const float*)d_in[11];
    const float* bn_b_be  = (const float*)d_in[12];
    const float* bn_b_m   = (const float*)d_in[13];
    const float* bn_b_v   = (const float*)d_in[14];
    const float* conv_d_w = (const float*)d_in[15];
    const float* conv_d_b = (const float*)d_in[16];
    const float* bn_g     = (const float*)d_in[17];
    const float* bn_be    = (const float*)d_in[18];
    const float* bn_m     = (const float*)d_in[19];
    const float* bn_v     = (const float*)d_in[20];
    float* out            = (float*)d_out;

    cudaFuncSetAttribute(k3_out, cudaFuncAttributeMaxDynamicSharedMemorySize, SMEM3);

    dim3 g1(TCH1, S_, N_);
    k1_conv_M<<<g1, 160>>>(x, conv_a_w, conv_a_b, conv_b_w, conv_b_b,
                           bn_a_g, bn_a_be, bn_a_m, bn_a_v,
                           bn_b_g, bn_b_be, bn_b_m, bn_b_v);

    dim3 g3(TCH3, N_);
    k3_out<<<g3, 256, SMEM3>>>(x, A, alpha, conv_d_w, conv_d_b,
                               bn_g, bn_be, bn_m, bn_v, out);
}

// round 2
// speedup vs baseline: 1.4176x; 1.4176x over previous
#include <cuda_runtime.h>

// ---------------------------------------------------------------------------
// unit_aagcn: N=64, C=OC=64, T=300, V=25, S=3, IC=16
// Packed f32x2 (FFMA2) version: accumulate pairs of adjacent t per instruction.
// ---------------------------------------------------------------------------

#define N_  64
#define C_  64
#define T_  300
#define V_  25
#define S_  3
#define IC_ 16

#define TCH1 5           // K1 t-chunks (60 t per block, 4 at a time)
#define T1   (T_ / TCH1) // 60
#define TCH3 15          // K3 t-chunks (20 t per block, 2 at a time)
#define T3   (T_ / TCH3) // 20

typedef unsigned long long u64;

__device__ float g_Mpart[N_ * S_ * TCH1 * V_ * V_];

__device__ __forceinline__ u64 pack2(float lo, float hi) {
    u64 r; asm("mov.b64 %0, {%1, %2};" : "=l"(r) : "f"(lo), "f"(hi)); return r;
}
__device__ __forceinline__ u64 bcast2(float v) {
    u64 r; asm("mov.b64 %0, {%1, %1};" : "=l"(r) : "f"(v)); return r;
}
__device__ __forceinline__ void unpack2(u64 p, float& lo, float& hi) {
    asm("mov.b64 {%0, %1}, %2;" : "=f"(lo), "=f"(hi) : "l"(p));
}
__device__ __forceinline__ u64 ffma2(u64 a, u64 b, u64 c) {
    u64 d; asm("fma.rn.f32x2 %0, %1, %2, %3;" : "=l"(d) : "l"(a), "l"(b), "l"(c));
    return d;
}

__device__ __forceinline__ float fast_tanh(float x) {
    float e = __expf(2.0f * x);
    return 1.0f - __fdividef(2.0f, e + 1.0f);
}

// ---------------------------------------------------------------------------
// K1: one block per (t-chunk, s, n). 160 threads. 4 t per iteration.
// ---------------------------------------------------------------------------
__global__ void __launch_bounds__(160)
k1_conv_M(const float* __restrict__ x,
          const float* __restrict__ wa, const float* __restrict__ ba,
          const float* __restrict__ wb, const float* __restrict__ bb,
          const float* __restrict__ ga, const float* __restrict__ bea,
          const float* __restrict__ ma, const float* __restrict__ va,
          const float* __restrict__ gb, const float* __restrict__ beb,
          const float* __restrict__ mb, const float* __restrict__ vb)
{
    const int tc = blockIdx.x;
    const int s  = blockIdx.y;
    const int n  = blockIdx.z;
    const int tid = threadIdx.x;

    __shared__ float WaT[C_ * IC_];   // [c][i]
    __shared__ float WbT[C_ * IC_];
    __shared__ float sA[IC_], cA[IC_], sB[IC_], cB[IC_];
    __shared__ u64 xs2[C_ * 50];      // [c][pr(2)][v(25)] packed (t0+2pr, t0+2pr+1)
    __shared__ u64 a2[2 * IC_ * V_];  // [pr][i][v] packed pair
    __shared__ u64 b2[2 * IC_ * V_];

    for (int idx = tid; idx < IC_ * C_; idx += 160) {
        int i = idx / C_, c = idx % C_;
        WaT[c * IC_ + i] = wa[(s * IC_ + i) * C_ + c];
        WbT[c * IC_ + i] = wb[(s * IC_ + i) * C_ + c];
    }
    if (tid < IC_) {
        int i = tid;
        float sa = ga[s * IC_ + i] * rsqrtf(va[s * IC_ + i] + 1e-5f);
        sA[i] = sa;
        cA[i] = sa * (ba[s * IC_ + i] - ma[s * IC_ + i]) + bea[s * IC_ + i];
        float sb = gb[s * IC_ + i] * rsqrtf(vb[s * IC_ + i] + 1e-5f);
        sB[i] = sb;
        cB[i] = sb * (bb[s * IC_ + i] - mb[s * IC_ + i]) + beb[s * IC_ + i];
    }

    // conv-phase mapping: 160 = 2 pr * 16 i * 5 vg
    const int pr = tid / 80;
    const int r  = tid % 80;
    const int ii = r & 15;
    const int vg = r >> 4;
    // M-phase mapping (threads < 125)
    const int vv = tid / 5;
    const int wg = tid % 5;

    u64 m2[5] = {0ull, 0ull, 0ull, 0ull, 0ull};
    const int t0 = tc * T1;
    __syncthreads();

    for (int tp = 0; tp < T1; tp += 4) {
        const int t = t0 + tp;
        // load x[n, :, t..t+3, :] packed into xs2
        for (int idx = tid; idx < C_ * 50; idx += 160) {
            int c = idx / 50, rr = idx % 50;
            int p = rr / 25, v = rr % 25;
            const float* gp = x + ((n * C_ + c) * T_ + t + 2 * p) * V_ + v;
            xs2[idx] = pack2(gp[0], gp[V_]);
        }
        __syncthreads();

        {
            u64 acca[5] = {0,0,0,0,0};
            u64 accb[5] = {0,0,0,0,0};
            const u64* xrow = xs2 + pr * 25 + vg * 5;
            #pragma unroll 8
            for (int c = 0; c < C_; c++) {
                u64 wa2 = bcast2(WaT[c * IC_ + ii]);
                u64 wb2 = bcast2(WbT[c * IC_ + ii]);
                #pragma unroll
                for (int k = 0; k < 5; k++) {
                    u64 xv = xrow[c * 50 + k];
                    acca[k] = ffma2(wa2, xv, acca[k]);
                    accb[k] = ffma2(wb2, xv, accb[k]);
                }
            }
            float sa = sA[ii], ca = cA[ii], sb = sB[ii], cb = cB[ii];
            u64* ap = a2 + (pr * IC_ + ii) * V_ + vg * 5;
            u64* bp = b2 + (pr * IC_ + ii) * V_ + vg * 5;
            #pragma unroll
            for (int k = 0; k < 5; k++) {
                float lo, hi;
                unpack2(acca[k], lo, hi);
                ap[k] = pack2(fast_tanh(fmaf(sa, lo, ca)), fast_tanh(fmaf(sa, hi, ca)));
                unpack2(accb[k], lo, hi);
                bp[k] = pack2(fast_tanh(fmaf(sb, lo, cb)), fast_tanh(fmaf(sb, hi, cb)));
            }
        }
        __syncthreads();

        if (tid < 125) {
            #pragma unroll
            for (int p = 0; p < 2; p++) {
                const u64* ap = a2 + p * IC_ * V_;
                const u64* bp = b2 + p * IC_ * V_ + wg * 5;
                #pragma unroll 4
                for (int i = 0; i < IC_; i++) {
                    u64 av = ap[i * V_ + vv];
                    #pragma unroll
                    for (int k = 0; k < 5; k++)
                        m2[k] = ffma2(av, bp[i * V_ + k], m2[k]);
                }
            }
        }
        __syncthreads();
    }

    if (tid < 125) {
        float* dst = g_Mpart + ((((n * S_ + s) * TCH1 + tc) * V_ + vv) * V_) + wg * 5;
        #pragma unroll
        for (int k = 0; k < 5; k++) {
            float lo, hi;
            unpack2(m2[k], lo, hi);
            dst[k] = lo + hi;
        }
    }
}

// ---------------------------------------------------------------------------
// K3: one block per (t-chunk, n). 256 threads. 2 t per iteration (packed).
// ---------------------------------------------------------------------------
#define WDP 68                                   // padded o-row for WdT
#define OFF_WDT   0                              // 3*64*68*4 = 52224  [s][c][o]
#define OFF_AA    52224                          // 7500 -> 7504
#define OFF_XS    (52224 + 7504)                 // u64[64*25] = 12800
#define OFF_ZS    (OFF_XS + 12800)               // u64[3*25*64] = 38400
#define OFF_SC    (OFF_ZS + 38400)               // 256
#define OFF_SH    (OFF_SC + 256)                 // 256
#define SMEM3     (OFF_SH + 256)

__global__ void __launch_bounds__(256, 2)
k3_out(const float* __restrict__ x,
       const float* __restrict__ A, const float* __restrict__ alpha,
       const float* __restrict__ wd, const float* __restrict__ bd,
       const float* __restrict__ bng, const float* __restrict__ bnb,
       const float* __restrict__ bnm, const float* __restrict__ bnv,
       float* __restrict__ out)
{
    extern __shared__ char smem[];
    float* WdT = (float*)(smem + OFF_WDT);   // [s][c][WDP]
    float* Aa  = (float*)(smem + OFF_AA);    // [s][v][w]
    u64*   xs2 = (u64*)  (smem + OFF_XS);    // [c][v] packed (t, t+1)
    u64*   zs2 = (u64*)  (smem + OFF_ZS);    // [(s*25+v)][o] packed
    float* scl = (float*)(smem + OFF_SC);
    float* shf = (float*)(smem + OFF_SH);

    const int tc  = blockIdx.x;
    const int n   = blockIdx.y;
    const int tid = threadIdx.x;

    for (int idx = tid; idx < S_ * C_ * C_; idx += 256) {
        int s = idx >> 12, rem = idx & 4095, o = rem >> 6, c = rem & 63;
        WdT[(s * C_ + c) * WDP + o] = wd[idx];
    }
    {
        float al = alpha[0];
        for (int idx = tid; idx < S_ * V_ * V_; idx += 256) {
            int s = idx / (V_ * V_), vwi = idx % (V_ * V_);
            const float* mp = g_Mpart + ((n * S_ + s) * TCH1) * (V_ * V_) + vwi;
            float msum = 0.f;
            #pragma unroll
            for (int p = 0; p < TCH1; p++) msum += mp[p * (V_ * V_)];
            Aa[idx] = A[idx] + tanhf(msum * (1.0f / (IC_ * T_))) * al;
        }
    }
    if (tid < C_) {
        float sc = bng[tid] * rsqrtf(bnv[tid] + 1e-5f);
        float db = bd[tid] + bd[C_ + tid] + bd[2 * C_ + tid];
        scl[tid] = sc;
        shf[tid] = bnb[tid] + sc * (db - bnm[tid]);
    }

    // phase Z mapping (tid<240): (s, o-group of 4, v-group of 5)
    const int sZ  = tid / 80;
    const int rZ  = tid % 80;
    const int ogZ = rZ & 15;
    const int vgZ = rZ >> 4;
    // phase Y mapping (tid<160): (o-pair, w-group of 5)
    const int ogY = tid & 31;
    const int wgY = tid >> 5;

    const int t0 = tc * T3;
    __syncthreads();

    for (int tp = 0; tp < T3; tp += 2) {
        const int t = t0 + tp;
        for (int idx = tid; idx < C_ * V_; idx += 256) {
            int c = idx / V_, v = idx % V_;
            const float* gp = x + ((n * C_ + c) * T_ + t) * V_ + v;
            xs2[idx] = pack2(gp[0], gp[V_]);
        }
        __syncthreads();

        // phase Z: z[s][v][o] = sum_c Wd[s][o][c] * x[c][v]  (packed t-pair)
        if (tid < 240) {
            u64 acc[4][5];
            #pragma unroll
            for (int j = 0; j < 4; j++)
                #pragma unroll
                for (int k = 0; k < 5; k++) acc[j][k] = 0ull;

            const float* wbase = WdT + sZ * C_ * WDP + ogZ * 4;
            const u64*   xbase = xs2 + vgZ * 5;
            #pragma unroll 4
            for (int c = 0; c < C_; c++) {
                float4 w4 = *(const float4*)(wbase + c * WDP);
                u64 w0 = bcast2(w4.x), w1 = bcast2(w4.y);
                u64 w2 = bcast2(w4.z), w3 = bcast2(w4.w);
                const u64* xc = xbase + c * V_;
                #pragma unroll
                for (int k = 0; k < 5; k++) {
                    u64 xv = xc[k];
                    acc[0][k] = ffma2(w0, xv, acc[0][k]);
                    acc[1][k] = ffma2(w1, xv, acc[1][k]);
                    acc[2][k] = ffma2(w2, xv, acc[2][k]);
                    acc[3][k] = ffma2(w3, xv, acc[3][k]);
                }
            }
            #pragma unroll
            for (int k = 0; k < 5; k++) {
                u64* zp = zs2 + ((sZ * V_ + vgZ * 5 + k) << 6) + ogZ * 4;
                ulonglong2 p0; p0.x = acc[0][k]; p0.y = acc[1][k];
                ulonglong2 p1; p1.x = acc[2][k]; p1.y = acc[3][k];
                *(ulonglong2*)(zp)     = p0;
                *(ulonglong2*)(zp + 2) = p1;
            }
        }
        __syncthreads();

        // phase Y: y[o][w] = sum_{s,v} z[s][v][o] * Aa[s][v][w] + epilogue
        if (tid < 160) {
            u64 acc[2][5];
            #pragma unroll
            for (int j = 0; j < 2; j++)
                #pragma unroll
                for (int k = 0; k < 5; k++) acc[j][k] = 0ull;

            #pragma unroll 5
            for (int sv = 0; sv < S_ * V_; sv++) {
                ulonglong2 z2 = *(const ulonglong2*)(zs2 + (sv << 6) + ogY * 2);
                const float* ar = Aa + sv * V_ + wgY * 5;
                #pragma unroll
                for (int k = 0; k < 5; k++) {
                    u64 aw = bcast2(ar[k]);
                    acc[0][k] = ffma2(z2.x, aw, acc[0][k]);
                    acc[1][k] = ffma2(z2.y, aw, acc[1][k]);
                }
            }
            #pragma unroll
            for (int j = 0; j < 2; j++) {
                int o = ogY * 2 + j;
                float sc = scl[o], sh = shf[o];
                float* op = out + ((n * C_ + o) * T_ + t) * V_ + wgY * 5;
                const u64* xr = xs2 + o * V_ + wgY * 5;
                #pragma unroll
                for (int k = 0; k < 5; k++) {
                    float alo, ahi, xlo, xhi;
                    unpack2(acc[j][k], alo, ahi);
                    unpack2(xr[k], xlo, xhi);
                    op[k]      = fmaxf(fmaf(sc, alo, sh) + xlo, 0.0f);
                    op[k + V_] = fmaxf(fmaf(sc, ahi, sh) + xhi, 0.0f);
                }
            }
        }
        __syncthreads();
    }
}

// ---------------------------------------------------------------------------
extern "C" void kernel_launch(void* const* d_in, const int* in_sizes, int n_in,
                              void* d_out, int out_size)
{
    const float* x        = (const float*)d_in[0];
    const float* A        = (const float*)d_in[1];
    const float* alpha    = (const float*)d_in[2];
    const float* conv_a_w = (const float*)d_in[3];
    const float* conv_a_b = (const float*)d_in[4];
    const float* conv_b_w = (const float*)d_in[5];
    const float* conv_b_b = (const float*)d_in[6];
    const float* bn_a_g   = (const float*)d_in[7];
    const float* bn_a_be  = (const float*)d_in[8];
    const float* bn_a_m   = (const float*)d_in[9];
    const float* bn_a_v   = (const float*)d_in[10];
    const float* bn_b_g   = (const float*)d_in[11];
    const float* bn_b_be  = (const float*)d_in[12];
    const float* bn_b_m   = (const float*)d_in[13];
    const float* bn_b_v   = (const float*)d_in[14];
    const float* conv_d_w = (const float*)d_in[15];
    const float* conv_d_b = (const float*)d_in[16];
    const float* bn_g     = (const float*)d_in[17];
    const float* bn_be    = (const float*)d_in[18];
    const float* bn_m     = (const float*)d_in[19];
    const float* bn_v     = (const float*)d_in[20];
    float* out            = (float*)d_out;

    cudaFuncSetAttribute(k3_out, cudaFuncAttributeMaxDynamicSharedMemorySize, SMEM3);

    dim3 g1(TCH1, S_, N_);
    k1_conv_M<<<g1, 160>>>(x, conv_a_w, conv_a_b, conv_b_w, conv_b_b,
                           bn_a_g, bn_a_be, bn_a_m, bn_a_v,
                           bn_b_g, bn_b_be, bn_b_m, bn_b_v);

    dim3 g3(TCH3, N_);
    k3_out<<<g3, 256, SMEM3>>>(x, A, alpha, conv_d_w, conv_d_b,
                               bn_g, bn_be, bn_m, bn_v, out);
}